// round 14
// baseline (speedup 1.0000x reference)
#include <cuda_runtime.h>
#include <cuda_bf16.h>
#include <cstdint>
#include <math.h>

#define NB 8
#define CC 256
#define TT 120
#define VVC 25
#define PP (NB*TT*VVC)   // 24000 points
#define TV (TT*VVC)      // 3000
#define HH 8
#define HD 32
#define LLN 125
#define EPSV 1e-5f

#define WQ_OFF 0
#define WO_OFF 196608
#define W1_OFF 262144
#define W2_OFF 327680
#define WTOT   393216

// Scratch (device globals; no allocation anywhere)
__device__ __align__(16) __nv_bfloat16 g_qkvh[PP*768];   // qkv split planes
__device__ __align__(16) __nv_bfloat16 g_qkvl[PP*768];
__device__ __align__(16) __nv_bfloat16 xs_h[PP*256];     // x transposed+split
__device__ __align__(16) __nv_bfloat16 xs_l[PP*256];
__device__ __align__(16) __nv_bfloat16 g_aoh[PP*256];    // attention out planes
__device__ __align__(16) __nv_bfloat16 g_aol[PP*256];
__device__ __align__(16) __nv_bfloat16 g_inth[PP*256];   // bn1 out planes
__device__ __align__(16) __nv_bfloat16 g_intl[PP*256];
__device__ __align__(16) __nv_bfloat16 g_h1h[PP*256];    // ffn mid planes
__device__ __align__(16) __nv_bfloat16 g_h1l[PP*256];
__device__ __align__(16) __nv_bfloat16 wsp_h[WTOT];      // weights [out][in]
__device__ __align__(16) __nv_bfloat16 wsp_l[WTOT];

// ---------------------------------------------------------------------------
__device__ __forceinline__ void cp16(void* dst, const void* src) {
    unsigned int d = (unsigned int)__cvta_generic_to_shared(dst);
    asm volatile("cp.async.cg.shared.global [%0], [%1], 16;\n" :: "r"(d), "l"(src));
}
// conditional copy: pred ? 16B copy : zero-fill 16B
__device__ __forceinline__ void cp16z(void* dst, const void* src, bool pred) {
    unsigned int d = (unsigned int)__cvta_generic_to_shared(dst);
    int sz = pred ? 16 : 0;
    asm volatile("cp.async.cg.shared.global [%0], [%1], 16, %2;\n"
                 :: "r"(d), "l"(src), "r"(sz));
}
#define CP_COMMIT() asm volatile("cp.async.commit_group;\n" ::: "memory")
#define CP_WAIT1()  asm volatile("cp.async.wait_group 1;\n" ::: "memory")
#define CP_WAIT0()  asm volatile("cp.async.wait_group 0;\n" ::: "memory")

#define MMA_BF16(c, a0, a1, a2, a3, b0, b1) \
    asm volatile("mma.sync.aligned.m16n8k16.row.col.f32.bf16.bf16.f32 " \
        "{%0,%1,%2,%3}, {%4,%5,%6,%7}, {%8,%9}, {%0,%1,%2,%3};" \
        : "+f"((c)[0]), "+f"((c)[1]), "+f"((c)[2]), "+f"((c)[3]) \
        : "r"(a0), "r"(a1), "r"(a2), "r"(a3), "r"(b0), "r"(b1))

#define LDMX4(r0, r1, r2, r3, addr) \
    asm volatile("ldmatrix.sync.aligned.m8n8.x4.shared.b16 {%0,%1,%2,%3}, [%4];" \
        : "=r"(r0), "=r"(r1), "=r"(r2), "=r"(r3) : "r"(addr))

#define LDMX4T(r0, r1, r2, r3, addr) \
    asm volatile("ldmatrix.sync.aligned.m8n8.x4.trans.shared.b16 {%0,%1,%2,%3}, [%4];" \
        : "=r"(r0), "=r"(r1), "=r"(r2), "=r"(r3) : "r"(addr))

__device__ __forceinline__ void store_split2(__nv_bfloat16* dh, __nv_bfloat16* dl,
                                             size_t o, float v0, float v1) {
    __nv_bfloat16 h0 = __float2bfloat16_rn(v0);
    __nv_bfloat16 h1 = __float2bfloat16_rn(v1);
    __nv_bfloat162 hp; hp.x = h0; hp.y = h1;
    __nv_bfloat162 lp;
    lp.x = __float2bfloat16_rn(v0 - __bfloat162float(h0));
    lp.y = __float2bfloat16_rn(v1 - __bfloat162float(h1));
    *(__nv_bfloat162*)&dh[o] = hp;
    *(__nv_bfloat162*)&dl[o] = lp;
}
__device__ __forceinline__ float2 load_split2(const __nv_bfloat16* dh,
                                              const __nv_bfloat16* dl, size_t o) {
    __nv_bfloat162 h = *(const __nv_bfloat162*)&dh[o];
    __nv_bfloat162 l = *(const __nv_bfloat162*)&dl[o];
    return make_float2(__bfloat162float(h.x) + __bfloat162float(l.x),
                       __bfloat162float(h.y) + __bfloat162float(l.y));
}

// ---------------------------------------------------------------------------
// prep_w / prep_x (unchanged)
// ---------------------------------------------------------------------------
__global__ __launch_bounds__(256) void prep_w(const float* __restrict__ wq,
                                              const float* __restrict__ wo,
                                              const float* __restrict__ w1,
                                              const float* __restrict__ w2)
{
    int idx = blockIdx.x * 256 + threadIdx.x;
    if (idx >= WTOT) return;
    float v;
    if (idx < WO_OFF)      { int j = idx >> 8, k = idx & 255; v = wq[k*768 + j]; }
    else if (idx < W1_OFF) { int l = idx - WO_OFF; int j = l >> 8, k = l & 255; v = wo[k*256 + j]; }
    else if (idx < W2_OFF) { v = w1[idx - W1_OFF]; }
    else                   { v = w2[idx - W2_OFF]; }
    __nv_bfloat16 h = __float2bfloat16_rn(v);
    wsp_h[idx] = h;
    wsp_l[idx] = __float2bfloat16_rn(v - __bfloat162float(h));
}

#define PXSMEM (2*64*264*2)   // 67584 bytes
__global__ __launch_bounds__(256) void prep_x(const float* __restrict__ x)
{
    extern __shared__ __nv_bfloat16 sx[];
    __nv_bfloat16* sh = sx;
    __nv_bfloat16* sl = sx + 64*264;
    const int tid = threadIdx.x;
    const int p0 = blockIdx.x * 64;
    #pragma unroll 4
    for (int it = 0; it < 64; ++it) {
        int lin = it * 256 + tid;
        int pl = lin & 63, cl = lin >> 6;
        int p = p0 + pl;
        int n = p / TV, r = p - n * TV;
        float v = x[(size_t)(n*CC + cl)*TV + r];
        __nv_bfloat16 h = __float2bfloat16_rn(v);
        sh[pl*264 + cl] = h;
        sl[pl*264 + cl] = __float2bfloat16_rn(v - __bfloat162float(h));
    }
    __syncthreads();
    #pragma unroll
    for (int s = tid; s < 2048; s += 256) {
        int pl = s >> 5, seg = s & 31;
        *(uint4*)&xs_h[(size_t)(p0+pl)*256 + seg*8] = *(uint4*)&sh[pl*264 + seg*8];
        *(uint4*)&xs_l[(size_t)(p0+pl)*256 + seg*8] = *(uint4*)&sl[pl*264 + seg*8];
    }
}

// ---------------------------------------------------------------------------
// mma_gemm v2: 256-point x 128-col tile, 512 threads (16 warps, wm 0..3).
// K=256 in 8 chunks of 32. Pre-split bf16 planes in, fused epilogues out.
// smem/stage (bf16 elems): Ah@0 [256][40], Al@10240, Bh@20480 [128][40],
// Bl@25600. GSTG=30720; 2 stages = 122880 B -> 1 CTA x 16 warps / SM.
// ---------------------------------------------------------------------------
#define GSTG 30720
#define GSMEM (2*GSTG*2)

template<int MODE>
__global__ __launch_bounds__(512)
void mma_gemm(const float* __restrict__ bias,
              const float* __restrict__ bg, const float* __restrict__ bb,
              const float* __restrict__ bm, const float* __restrict__ bv,
              float* __restrict__ outp)
{
    extern __shared__ __nv_bfloat16 smb[];

    const int tid  = threadIdx.x;
    const int lane = tid & 31;
    const int wid  = tid >> 5;
    const int wm   = wid >> 2;            // 0..3
    const int wn   = wid & 3;
    const int p0   = blockIdx.x * 256;
    const int jb   = blockIdx.y * 128;

    const __nv_bfloat16* Asrc_h;
    const __nv_bfloat16* Asrc_l;
    int woff;
    if constexpr (MODE == 0) { Asrc_h = xs_h;   Asrc_l = xs_l;   woff = WQ_OFF; }
    else if constexpr (MODE == 1) { Asrc_h = g_aoh;  Asrc_l = g_aol;  woff = WO_OFF; }
    else if constexpr (MODE == 2) { Asrc_h = g_inth; Asrc_l = g_intl; woff = W1_OFF; }
    else { Asrc_h = g_h1h; Asrc_l = g_h1l; woff = W2_OFF; }

    float acc[4][4][4];
    #pragma unroll
    for (int mi = 0; mi < 4; ++mi)
        #pragma unroll
        for (int ni = 0; ni < 4; ++ni)
            #pragma unroll
            for (int q = 0; q < 4; ++q) acc[mi][ni][q] = 0.f;

    auto fill = [&](int c, int st) {
        const int c0 = c * 32;
        __nv_bfloat16* Sg = smb + st * GSTG;
        #pragma unroll
        for (int i = 0; i < 6; ++i) {
            int s = i * 512 + tid;            // 0..3071
            if (s < 2048) {                   // A planes: 2 x 256 rows x 4 chunks
                int plane = s >> 10;
                int e = s & 1023;
                int row = e >> 2, sg = e & 3;
                int p = p0 + row; if (p >= PP) p = PP - 1;
                const __nv_bfloat16* src =
                    (plane ? Asrc_l : Asrc_h) + (size_t)p*256 + c0 + sg*8;
                cp16(&Sg[plane*10240 + row*40 + sg*8], src);
            } else {                          // B planes: 2 x 128 rows x 4 chunks
                int e = s - 2048;
                int plane = e >> 9;
                int ee = e & 511;
                int row = ee >> 2, sg = ee & 3;
                const __nv_bfloat16* src =
                    (plane ? wsp_l : wsp_h) + (size_t)woff + (size_t)(jb + row)*256 + c0 + sg*8;
                cp16(&Sg[20480 + plane*5120 + row*40 + sg*8], src);
            }
        }
    };

    // ldmatrix lane geometry
    const int rA = lane & 15;
    const int cA = (lane >> 4) * 8;
    const int rB = (lane & 7) + ((lane >> 4) * 8);
    const int cB = ((lane >> 3) & 1) * 8;

    auto compute = [&](int st) {
        const __nv_bfloat16* base = smb + st * GSTG;
        uint32_t sb = (uint32_t)__cvta_generic_to_shared(base);
        #pragma unroll
        for (int kh = 0; kh < 2; ++kh) {
            const int ko = kh * 16;
            uint32_t bh[4][2], bl[4][2];
            #pragma unroll
            for (int pi = 0; pi < 2; ++pi) {
                uint32_t ab = sb + (uint32_t)(20480 + (wn*32 + pi*16 + rB)*40 + ko + cB)*2;
                LDMX4(bh[2*pi][0], bh[2*pi][1], bh[2*pi+1][0], bh[2*pi+1][1], ab);
                LDMX4(bl[2*pi][0], bl[2*pi][1], bl[2*pi+1][0], bl[2*pi+1][1], ab + 5120*2);
            }
            #pragma unroll
            for (int mi = 0; mi < 4; ++mi) {
                uint32_t aa = sb + (uint32_t)((wm*64 + mi*16 + rA)*40 + ko + cA)*2;
                uint32_t ah0, ah1, ah2, ah3, al0, al1, al2, al3;
                LDMX4(ah0, ah1, ah2, ah3, aa);
                LDMX4(al0, al1, al2, al3, aa + 10240*2);
                #pragma unroll
                for (int ni = 0; ni < 4; ++ni) {
                    MMA_BF16(acc[mi][ni], ah0, ah1, ah2, ah3, bh[ni][0], bh[ni][1]);
                    MMA_BF16(acc[mi][ni], ah0, ah1, ah2, ah3, bl[ni][0], bl[ni][1]);
                    MMA_BF16(acc[mi][ni], al0, al1, al2, al3, bh[ni][0], bh[ni][1]);
                }
            }
        }
    };

    fill(0, 0); CP_COMMIT();
    int st = 0;
    #pragma unroll 1
    for (int c = 0; c < 8; ++c) {
        if (c < 7) { fill(c + 1, st ^ 1); CP_COMMIT(); CP_WAIT1(); }
        else       { CP_WAIT0(); }
        __syncthreads();
        compute(st);
        __syncthreads();
        st ^= 1;
    }

    const int fr = lane >> 2;
    const int fc = (lane & 3) * 2;

    if constexpr (MODE == 0) {
        #pragma unroll
        for (int mi = 0; mi < 4; ++mi) {
            int pr = p0 + wm*64 + mi*16 + fr;
            #pragma unroll
            for (int ni = 0; ni < 4; ++ni) {
                int jc = jb + wn*32 + ni*8 + fc;
                if (pr < PP)
                    store_split2(g_qkvh, g_qkvl, (size_t)pr*768 + jc,
                                 acc[mi][ni][0], acc[mi][ni][1]);
                if (pr + 8 < PP)
                    store_split2(g_qkvh, g_qkvl, (size_t)(pr+8)*768 + jc,
                                 acc[mi][ni][2], acc[mi][ni][3]);
            }
        }
        return;
    }

    float sc[4][2], be[4][2], bo[4][2];
    #pragma unroll
    for (int ni = 0; ni < 4; ++ni)
        #pragma unroll
        for (int q = 0; q < 2; ++q) {
            int j = jb + wn*32 + ni*8 + fc + q;
            float s = rsqrtf(bv[j] + EPSV) * bg[j];
            sc[ni][q] = s;
            be[ni][q] = bb[j] - bm[j] * s;
            bo[ni][q] = (MODE == 1) ? bias[j] : 0.f;
        }

    if constexpr (MODE == 1) {
        #pragma unroll
        for (int mi = 0; mi < 4; ++mi) {
            int pr = p0 + wm*64 + mi*16 + fr;
            #pragma unroll
            for (int ni = 0; ni < 4; ++ni) {
                int jc = jb + wn*32 + ni*8 + fc;
                if (pr < PP) {
                    size_t o = (size_t)pr*256 + jc;
                    float2 xr = load_split2(xs_h, xs_l, o);
                    float v0 = (acc[mi][ni][0] + bo[ni][0] + xr.x)*sc[ni][0] + be[ni][0];
                    float v1 = (acc[mi][ni][1] + bo[ni][1] + xr.y)*sc[ni][1] + be[ni][1];
                    store_split2(g_inth, g_intl, o, v0, v1);
                }
                if (pr + 8 < PP) {
                    size_t o = (size_t)(pr+8)*256 + jc;
                    float2 xr = load_split2(xs_h, xs_l, o);
                    float v2 = (acc[mi][ni][2] + bo[ni][0] + xr.x)*sc[ni][0] + be[ni][0];
                    float v3 = (acc[mi][ni][3] + bo[ni][1] + xr.y)*sc[ni][1] + be[ni][1];
                    store_split2(g_inth, g_intl, o, v2, v3);
                }
            }
        }
        return;
    }

    if constexpr (MODE == 2) {
        #pragma unroll
        for (int mi = 0; mi < 4; ++mi) {
            int pr = p0 + wm*64 + mi*16 + fr;
            #pragma unroll
            for (int ni = 0; ni < 4; ++ni) {
                int jc = jb + wn*32 + ni*8 + fc;
                float v[4];
                #pragma unroll
                for (int q = 0; q < 4; ++q) {
                    float a = acc[mi][ni][q];
                    float sp = (a > 20.f) ? a : log1pf(__expf(a));
                    v[q] = a * tanhf(sp) * sc[ni][q & 1] + be[ni][q & 1];
                }
                if (pr < PP)
                    store_split2(g_h1h, g_h1l, (size_t)pr*256 + jc, v[0], v[1]);
                if (pr + 8 < PP)
                    store_split2(g_h1h, g_h1l, (size_t)(pr+8)*256 + jc, v[2], v[3]);
            }
        }
        return;
    }

    // MODE 3: residual(split) + bn2, staged transpose, coalesced NCHW scatter
    float* stg = (float*)smb;   // [64][132] floats
    #pragma unroll 1
    for (int ph = 0; ph < 4; ++ph) {
        __syncthreads();
        if (wm == ph) {
            #pragma unroll
            for (int mi = 0; mi < 4; ++mi) {
                int lr = mi*16 + fr;
                int pr = p0 + ph*64 + lr;
                int p0c = (pr < PP) ? pr : PP - 1;
                int p1c = (pr + 8 < PP) ? pr + 8 : PP - 1;
                #pragma unroll
                for (int ni = 0; ni < 4; ++ni) {
                    int jl = wn*32 + ni*8 + fc;
                    float2 r0 = load_split2(g_inth, g_intl, (size_t)p0c*256 + jb + jl);
                    float2 r1 = load_split2(g_inth, g_intl, (size_t)p1c*256 + jb + jl);
                    stg[lr*132 + jl]       = (acc[mi][ni][0] + r0.x)*sc[ni][0] + be[ni][0];
                    stg[lr*132 + jl + 1]   = (acc[mi][ni][1] + r0.y)*sc[ni][1] + be[ni][1];
                    stg[(lr+8)*132 + jl]   = (acc[mi][ni][2] + r1.x)*sc[ni][0] + be[ni][0];
                    stg[(lr+8)*132 + jl+1] = (acc[mi][ni][3] + r1.y)*sc[ni][1] + be[ni][1];
                }
            }
        }
        __syncthreads();
        for (int idx = tid; idx < 64 * 128; idx += 512) {
            int pl = idx & 63, j = idx >> 6;
            int p = p0 + ph*64 + pl;
            if (p < PP) {
                int n = p / TV, r = p - n * TV;
                outp[(size_t)(n * CC + jb + j) * TV + r] = stg[pl*132 + j];
            }
        }
    }
}

// ---------------------------------------------------------------------------
// Attention v9: per-m gather offset table (kills per-task div/mod), phase-1
// cp.async from pre-split planes, QK/SV via ldmatrix.
// smem layout (bf16 elements):
//   QK planes: Qh@0 Ql@5120 Kh@10240 Kl@15360 (stride 40; phases 1-2)
//   P planes:  Ph@0 [128][136], Pl@17408 (overlay QK; phases 3-4)
//   V planes:  Vh@34816 [128][40], Vl@39936
//   T (float idx) @22528: [128][36]; s2d @27136 [4][128]; sums @27648 [128]
//   offs (int idx) @27776: [128]
// Total 27904 floats = 111616 B -> 2 CTAs/SM.
// ---------------------------------------------------------------------------
#define AT_PL   17408
#define AT_VH   34816
#define AT_VL   39936
#define AT_T    22528
#define AT_S2D  27136
#define AT_SUM  27648
#define AT_OFF  27776
#define ATTN_SMEM_FLOATS 27904

__global__ __launch_bounds__(256, 2)
void attn_kernel()
{
    extern __shared__ float smA[];
    __nv_bfloat16* bb_ = (__nv_bfloat16*)smA;
    __nv_bfloat16* Qh = bb_;                 // stride 40
    __nv_bfloat16* Ql = bb_ + 5120;
    __nv_bfloat16* Kh = bb_ + 10240;
    __nv_bfloat16* Kl = bb_ + 15360;
    __nv_bfloat16* Ph = bb_;                 // stride 136 (overlays QK planes)
    __nv_bfloat16* Pl = bb_ + AT_PL;
    __nv_bfloat16* Vh = bb_ + AT_VH;         // [m][40] row-major
    __nv_bfloat16* Vl = bb_ + AT_VL;
    float* T    = smA + AT_T;                // [128][36]
    float* s2d  = smA + AT_S2D;              // [4][128]
    float* sums = smA + AT_SUM;
    int*   offs = (int*)(smA + AT_OFF);      // [128]

    const int tid  = threadIdx.x;
    const int lane = tid & 31;
    const int wid  = tid >> 5;
    const int wm   = wid >> 2;
    const int wn   = wid & 3;
    const int bx = blockIdx.x, h = blockIdx.y;
    const int n = bx / TT, t = bx - n * TT;
    const int fr = lane >> 2;
    const int fc = (lane & 3) * 2;
    // ldmatrix lane geometry
    const int rA = lane & 15;
    const int cA = (lane >> 4) * 8;
    const int rB = (lane & 7) + ((lane >> 4) * 8);
    const int cB = ((lane >> 3) & 1) * 8;
    // trans (V) lane geometry
    const int rT = (lane & 7) + ((lane & 8) ? 8 : 0);
    const int cT = (lane >> 4) * 8;

    // ---- phase 0: per-m source offset table ----
    if (tid < 128) {
        int m = tid;
        int w = m / VVC, vv = m - w * VVC;
        int ti = t + w - 2;
        bool val = (m < LLN) && (ti >= 0) && (ti < TT);
        offs[m] = val ? (((n*TT + ti)*VVC + vv)*768 + h*96) : -1;
    }
    __syncthreads();

    // ---- phase 1: cp.async gathers (table lookup; zfill invalid rows) ----
    for (int lin = tid; lin < 2048; lin += 256) {
        int m = lin >> 4, c = lin & 15;      // c 0-7: q, 8-15: k
        int ofs = offs[m];
        bool val = ofs >= 0;
        int isq   = (c < 8);
        int plane = (c >> 2) & 1;            // 0: hi, 1: lo
        int chunk = c & 3;
        const __nv_bfloat16* srcb = plane ? g_qkvl : g_qkvh;
        __nv_bfloat16* dst = isq ? (plane ? Ql : Qh) : (plane ? Kl : Kh);
        cp16z(&dst[m*40 + chunk*8],
              &srcb[(size_t)(val ? ofs : 0) + (isq ? 0 : 32) + chunk*8], val);
    }
    for (int lin = tid; lin < 1024; lin += 256) {
        int m = lin >> 3, c = lin & 7;
        int ofs = offs[m];
        bool val = ofs >= 0;
        int plane = c >> 2, chunk = c & 3;
        const __nv_bfloat16* srcb = plane ? g_qkvl : g_qkvh;
        __nv_bfloat16* dst = plane ? Vl : Vh;
        cp16z(&dst[m*40 + chunk*8],
              &srcb[(size_t)(val ? ofs : 0) + 64 + chunk*8], val);
    }
    CP_COMMIT();
    CP_WAIT0();
    __syncthreads();

    // ---- phase 2: S = Q K^T (tensor cores, 3-MMA split, ldmatrix) ----
    float acc[4][4][4];
    #pragma unroll
    for (int mi = 0; mi < 4; ++mi)
        #pragma unroll
        for (int ni = 0; ni < 4; ++ni)
            #pragma unroll
            for (int q = 0; q < 4; ++q) acc[mi][ni][q] = 0.f;

    {
        uint32_t sq = (uint32_t)__cvta_generic_to_shared(Qh);
        #pragma unroll
        for (int kh = 0; kh < 2; ++kh) {
            const int ko = kh * 16;
            uint32_t bh[4][2], bl[4][2];
            #pragma unroll
            for (int pi = 0; pi < 2; ++pi) {
                uint32_t ab = sq + (uint32_t)(10240 + (wn*32 + pi*16 + rB)*40 + ko + cB)*2;
                LDMX4(bh[2*pi][0], bh[2*pi][1], bh[2*pi+1][0], bh[2*pi+1][1], ab);
                LDMX4(bl[2*pi][0], bl[2*pi][1], bl[2*pi+1][0], bl[2*pi+1][1], ab + 5120*2);
            }
            #pragma unroll
            for (int mi = 0; mi < 4; ++mi) {
                uint32_t aa = sq + (uint32_t)((wm*64 + mi*16 + rA)*40 + ko + cA)*2;
                uint32_t ah0, ah1, ah2, ah3, al0, al1, al2, al3;
                LDMX4(ah0, ah1, ah2, ah3, aa);
                LDMX4(al0, al1, al2, al3, aa + 5120*2);
                #pragma unroll
                for (int ni = 0; ni < 4; ++ni) {
                    MMA_BF16(acc[mi][ni], ah0, ah1, ah2, ah3, bh[ni][0], bh[ni][1]);
                    MMA_BF16(acc[mi][ni], ah0, ah1, ah2, ah3, bl[ni][0], bl[ni][1]);
                    MMA_BF16(acc[mi][ni], al0, al1, al2, al3, bh[ni][0], bh[ni][1]);
                }
            }
        }
    }
    __syncthreads();   // QK planes dead; safe to overlay P

    // ---- phase 3: exp in registers -> P planes + row-sum partials ----
    #pragma unroll
    for (int mi = 0; mi < 4; ++mi) {
        int r0 = wm*64 + mi*16 + fr;
        int r1 = r0 + 8;
        float s0 = 0.f, s1 = 0.f;
        #pragma unroll
        for (int ni = 0; ni < 4; ++ni) {
            int jc = wn*32 + ni*8 + fc;
            float p0 = (jc     >= LLN) ? 0.f : __expf(acc[mi][ni][0] * 0.0625f);
            float p1 = (jc + 1 >= LLN) ? 0.f : __expf(acc[mi][ni][1] * 0.0625f);
            float p2 = (jc     >= LLN) ? 0.f : __expf(acc[mi][ni][2] * 0.0625f);
            float p3 = (jc + 1 >= LLN) ? 0.f : __expf(acc[mi][ni][3] * 0.0625f);
            store_split2(Ph, Pl, (size_t)r0*136 + jc, p0, p1);
            store_split2(Ph, Pl, (size_t)r1*136 + jc, p2, p3);
            s0 += p0 + p1;
            s1 += p2 + p3;
        }
        s0 += __shfl_xor_sync(0xffffffffu, s0, 1);
        s0 += __shfl_xor_sync(0xffffffffu, s0, 2);
        s1 += __shfl_xor_sync(0xffffffffu, s1, 1);
        s1 += __shfl_xor_sync(0xffffffffu, s1, 2);
        if ((lane & 3) == 0) {
            s2d[wn*128 + r0] = s0;
            s2d[wn*128 + r1] = s1;
        }
    }
    __syncthreads();

    // ---- phase 4: combine row sums, then SV MMA: T = P.V ----
    if (tid < LLN)
        sums[tid] = 0.2f / (s2d[tid] + s2d[128 + tid] + s2d[256 + tid] + s2d[384 + tid]);

    float accS[4][4];
    #pragma unroll
    for (int ni = 0; ni < 4; ++ni)
        #pragma unroll
        for (int q = 0; q < 4; ++q) accS[ni][q] = 0.f;

    {
        uint32_t sp_ = (uint32_t)__cvta_generic_to_shared(Ph);
        uint32_t sv_ = (uint32_t)__cvta_generic_to_shared(Vh);
        #pragma unroll
        for (int kh = 0; kh < 8; ++kh) {
            const int ko = kh * 16;
            uint32_t bh[4][2], bl[4][2];
            #pragma unroll
            for (int pi = 0; pi < 2; ++pi) {
                uint32_t ab = sv_ + (uint32_t)((ko + rT)*40 + pi*16 + cT)*2;
                LDMX4T(bh[2*pi][0], bh[2*pi][1], bh[2*pi+1][0], bh[2*pi+1][1], ab);
                LDMX4T(bl[2*pi][0], bl[2*pi][1], bl[2*pi+1][0], bl[2*pi+1][1],
                       ab + (AT_VL - AT_VH)*2);
            }
            uint32_t aa = sp_ + (uint32_t)((wid*16 + rA)*136 + ko + cA)*2;
            uint32_t ah0, ah1, ah2, ah3, al0, al1, al2, al3;
            LDMX4(ah0, ah1, ah2, ah3, aa);
            LDMX4(al0, al1, al2, al3, aa + AT_PL*2);
            #pragma unroll
            for (int ni = 0; ni < 4; ++ni) {
                MMA_BF16(accS[ni], ah0, ah1, ah2, ah3, bh[ni][0], bh[ni][1]);
                MMA_BF16(accS[ni], ah0, ah1, ah2, ah3, bl[ni][0], bl[ni][1]);
                MMA_BF16(accS[ni], al0, al1, al2, al3, bh[ni][0], bh[ni][1]);
            }
        }
    }
    // write T
    #pragma unroll
    for (int ni = 0; ni < 4; ++ni) {
        int col = ni*8 + fc;
        int row = wid*16 + rA;   // == wid*16 + fr rows pattern below
        (void)row;
    }
    #pragma unroll
    for (int ni = 0; ni < 4; ++ni) {
        int col = ni*8 + fc;
        int row = wid*16 + fr;
        *(float2*)&T[row*36 + col]     = make_float2(accS[ni][0], accS[ni][1]);
        *(float2*)&T[(row+8)*36 + col] = make_float2(accS[ni][2], accS[ni][3]);
    }
    __syncthreads();

    // ---- phase 5: O[v,d] = sum_w T[w*25+v,d] * (0.2/sum) -> g_ao planes ----
    if (tid < 200) {
        const int v = tid >> 3, g = tid & 7;
        float4 a4 = make_float4(0.f, 0.f, 0.f, 0.f);
        #pragma unroll
        for (int w = 0; w < 5; ++w) {
            int l = w*VVC + v;
            float rs = sums[l];
            float4 tv = *(const float4*)&T[l*36 + g*4];
            a4.x = fmaf(tv.x, rs, a4.x); a4.y = fmaf(tv.y, rs, a4.y);
            a4.z = fmaf(tv.z, rs, a4.z); a4.w = fmaf(tv.w, rs, a4.w);
        }
        size_t base = ((size_t)((n*TT + t)*VVC + v))*256 + h*HD + g*4;
        store_split2(g_aoh, g_aol, base,     a4.x, a4.y);
        store_split2(g_aoh, g_aol, base + 2, a4.z, a4.w);
    }
}

// ---------------------------------------------------------------------------
extern "C" void kernel_launch(void* const* d_in, const int* in_sizes, int n_in,
                              void* d_out, int out_size)
{
    const float* x      = (const float*)d_in[0];
    const float* w_qkv  = (const float*)d_in[1];
    const float* w_out  = (const float*)d_in[2];
    const float* b_out  = (const float*)d_in[3];
    const float* bn1_g  = (const float*)d_in[4];
    const float* bn1_b  = (const float*)d_in[5];
    const float* ffn_w1 = (const float*)d_in[6];
    const float* ffn_w2 = (const float*)d_in[7];
    const float* ffn_g  = (const float*)d_in[8];
    const float* ffn_b  = (const float*)d_in[9];
    const float* bn2_g  = (const float*)d_in[10];
    const float* bn2_b  = (const float*)d_in[11];
    const float* bn1_m  = (const float*)d_in[12];
    const float* bn1_v  = (const float*)d_in[13];
    const float* ffn_m  = (const float*)d_in[14];
    const float* ffn_v  = (const float*)d_in[15];
    const float* bn2_m  = (const float*)d_in[16];
    const float* bn2_v  = (const float*)d_in[17];
    float* out = (float*)d_out;

    static int attr_done = 0;
    if (!attr_done) {
        cudaFuncSetAttribute(attn_kernel,
            cudaFuncAttributeMaxDynamicSharedMemorySize, ATTN_SMEM_FLOATS * 4);
        cudaFuncSetAttribute(prep_x,
            cudaFuncAttributeMaxDynamicSharedMemorySize, PXSMEM);
        cudaFuncSetAttribute(mma_gemm<0>,
            cudaFuncAttributeMaxDynamicSharedMemorySize, GSMEM);
        cudaFuncSetAttribute(mma_gemm<1>,
            cudaFuncAttributeMaxDynamicSharedMemorySize, GSMEM);
        cudaFuncSetAttribute(mma_gemm<2>,
            cudaFuncAttributeMaxDynamicSharedMemorySize, GSMEM);
        cudaFuncSetAttribute(mma_gemm<3>,
            cudaFuncAttributeMaxDynamicSharedMemorySize, GSMEM);
        attr_done = 1;
    }

    const int MT = (PP + 255) / 256;   // 94 M-tiles

    prep_w<<<(WTOT + 255)/256, 256>>>(w_qkv, w_out, ffn_w1, ffn_w2);
    prep_x<<<PP/64, 256, PXSMEM>>>(x);

    mma_gemm<0><<<dim3(MT, 6), 512, GSMEM>>>(
        nullptr, nullptr, nullptr, nullptr, nullptr, nullptr);

    attn_kernel<<<dim3(NB*TT, HH), 256, ATTN_SMEM_FLOATS * 4>>>();

    mma_gemm<1><<<dim3(MT, 2), 512, GSMEM>>>(
        b_out, bn1_g, bn1_b, bn1_m, bn1_v, nullptr);

    mma_gemm<2><<<dim3(MT, 2), 512, GSMEM>>>(
        nullptr, ffn_g, ffn_b, ffn_m, ffn_v, nullptr);

    mma_gemm<3><<<dim3(MT, 2), 512, GSMEM>>>(
        nullptr, bn2_g, bn2_b, bn2_m, bn2_v, out);
}

// round 15
// speedup vs baseline: 1.1261x; 1.1261x over previous
#include <cuda_runtime.h>
#include <cuda_bf16.h>
#include <cstdint>
#include <math.h>

#define NB 8
#define CC 256
#define TT 120
#define VVC 25
#define PP (NB*TT*VVC)   // 24000 points
#define TV (TT*VVC)      // 3000
#define HH 8
#define HD 32
#define LLN 125
#define EPSV 1e-5f

#define WQ_OFF 0
#define WO_OFF 196608
#define W1_OFF 262144
#define W2_OFF 327680
#define WTOT   393216

// Scratch (device globals; no allocation anywhere)
__device__ __align__(16) __nv_bfloat16 g_qkvh[PP*768];   // qkv split planes
__device__ __align__(16) __nv_bfloat16 g_qkvl[PP*768];
__device__ __align__(16) __nv_bfloat16 xs_h[PP*256];     // x transposed+split
__device__ __align__(16) __nv_bfloat16 xs_l[PP*256];
__device__ __align__(16) __nv_bfloat16 g_aoh[PP*256];    // attention out planes
__device__ __align__(16) __nv_bfloat16 g_aol[PP*256];
__device__ __align__(16) __nv_bfloat16 g_inth[PP*256];   // bn1 out planes
__device__ __align__(16) __nv_bfloat16 g_intl[PP*256];
__device__ __align__(16) __nv_bfloat16 g_h1h[PP*256];    // ffn mid planes
__device__ __align__(16) __nv_bfloat16 g_h1l[PP*256];
__device__ __align__(16) __nv_bfloat16 wsp_h[WTOT];      // weights [out][in]
__device__ __align__(16) __nv_bfloat16 wsp_l[WTOT];

// ---------------------------------------------------------------------------
__device__ __forceinline__ void cp16(void* dst, const void* src) {
    unsigned int d = (unsigned int)__cvta_generic_to_shared(dst);
    asm volatile("cp.async.cg.shared.global [%0], [%1], 16;\n" :: "r"(d), "l"(src));
}
// conditional copy: pred ? 16B copy : zero-fill 16B
__device__ __forceinline__ void cp16z(void* dst, const void* src, bool pred) {
    unsigned int d = (unsigned int)__cvta_generic_to_shared(dst);
    int sz = pred ? 16 : 0;
    asm volatile("cp.async.cg.shared.global [%0], [%1], 16, %2;\n"
                 :: "r"(d), "l"(src), "r"(sz));
}
#define CP_COMMIT() asm volatile("cp.async.commit_group;\n" ::: "memory")
#define CP_WAIT1()  asm volatile("cp.async.wait_group 1;\n" ::: "memory")
#define CP_WAIT0()  asm volatile("cp.async.wait_group 0;\n" ::: "memory")

#define MMA_BF16(c, a0, a1, a2, a3, b0, b1) \
    asm volatile("mma.sync.aligned.m16n8k16.row.col.f32.bf16.bf16.f32 " \
        "{%0,%1,%2,%3}, {%4,%5,%6,%7}, {%8,%9}, {%0,%1,%2,%3};" \
        : "+f"((c)[0]), "+f"((c)[1]), "+f"((c)[2]), "+f"((c)[3]) \
        : "r"(a0), "r"(a1), "r"(a2), "r"(a3), "r"(b0), "r"(b1))

#define LDMX4(r0, r1, r2, r3, addr) \
    asm volatile("ldmatrix.sync.aligned.m8n8.x4.shared.b16 {%0,%1,%2,%3}, [%4];" \
        : "=r"(r0), "=r"(r1), "=r"(r2), "=r"(r3) : "r"(addr))

#define LDMX4T(r0, r1, r2, r3, addr) \
    asm volatile("ldmatrix.sync.aligned.m8n8.x4.trans.shared.b16 {%0,%1,%2,%3}, [%4];" \
        : "=r"(r0), "=r"(r1), "=r"(r2), "=r"(r3) : "r"(addr))

__device__ __forceinline__ void store_split2(__nv_bfloat16* dh, __nv_bfloat16* dl,
                                             size_t o, float v0, float v1) {
    __nv_bfloat16 h0 = __float2bfloat16_rn(v0);
    __nv_bfloat16 h1 = __float2bfloat16_rn(v1);
    __nv_bfloat162 hp; hp.x = h0; hp.y = h1;
    __nv_bfloat162 lp;
    lp.x = __float2bfloat16_rn(v0 - __bfloat162float(h0));
    lp.y = __float2bfloat16_rn(v1 - __bfloat162float(h1));
    *(__nv_bfloat162*)&dh[o] = hp;
    *(__nv_bfloat162*)&dl[o] = lp;
}
__device__ __forceinline__ float2 load_split2(const __nv_bfloat16* dh,
                                              const __nv_bfloat16* dl, size_t o) {
    __nv_bfloat162 h = *(const __nv_bfloat162*)&dh[o];
    __nv_bfloat162 l = *(const __nv_bfloat162*)&dl[o];
    return make_float2(__bfloat162float(h.x) + __bfloat162float(l.x),
                       __bfloat162float(h.y) + __bfloat162float(l.y));
}

// ---------------------------------------------------------------------------
// prep_w / prep_x
// ---------------------------------------------------------------------------
__global__ __launch_bounds__(256) void prep_w(const float* __restrict__ wq,
                                              const float* __restrict__ wo,
                                              const float* __restrict__ w1,
                                              const float* __restrict__ w2)
{
    int idx = blockIdx.x * 256 + threadIdx.x;
    if (idx >= WTOT) return;
    float v;
    if (idx < WO_OFF)      { int j = idx >> 8, k = idx & 255; v = wq[k*768 + j]; }
    else if (idx < W1_OFF) { int l = idx - WO_OFF; int j = l >> 8, k = l & 255; v = wo[k*256 + j]; }
    else if (idx < W2_OFF) { v = w1[idx - W1_OFF]; }
    else                   { v = w2[idx - W2_OFF]; }
    __nv_bfloat16 h = __float2bfloat16_rn(v);
    wsp_h[idx] = h;
    wsp_l[idx] = __float2bfloat16_rn(v - __bfloat162float(h));
}

#define PXSMEM (2*64*264*2)   // 67584 bytes
__global__ __launch_bounds__(256) void prep_x(const float* __restrict__ x)
{
    extern __shared__ __nv_bfloat16 sx[];
    __nv_bfloat16* sh = sx;
    __nv_bfloat16* sl = sx + 64*264;
    const int tid = threadIdx.x;
    const int p0 = blockIdx.x * 64;
    #pragma unroll 4
    for (int it = 0; it < 64; ++it) {
        int lin = it * 256 + tid;
        int pl = lin & 63, cl = lin >> 6;
        int p = p0 + pl;
        int n = p / TV, r = p - n * TV;
        float v = x[(size_t)(n*CC + cl)*TV + r];
        __nv_bfloat16 h = __float2bfloat16_rn(v);
        sh[pl*264 + cl] = h;
        sl[pl*264 + cl] = __float2bfloat16_rn(v - __bfloat162float(h));
    }
    __syncthreads();
    #pragma unroll
    for (int s = tid; s < 2048; s += 256) {
        int pl = s >> 5, seg = s & 31;
        *(uint4*)&xs_h[(size_t)(p0+pl)*256 + seg*8] = *(uint4*)&sh[pl*264 + seg*8];
        *(uint4*)&xs_l[(size_t)(p0+pl)*256 + seg*8] = *(uint4*)&sl[pl*264 + seg*8];
    }
}

// ---------------------------------------------------------------------------
// mma_gemm (round-13 config: 128-point tile, 256 threads, 2 CTAs/SM,
// ldmatrix fragment loads, pre-split plane inputs, fused epilogues).
// ---------------------------------------------------------------------------
#define GSTG 20480
#define GSMEM (2*GSTG*2)

template<int MODE>
__global__ __launch_bounds__(256)
void mma_gemm(const float* __restrict__ bias,
              const float* __restrict__ bg, const float* __restrict__ bb,
              const float* __restrict__ bm, const float* __restrict__ bv,
              float* __restrict__ outp)
{
    extern __shared__ __nv_bfloat16 smb[];

    const int tid  = threadIdx.x;
    const int lane = tid & 31;
    const int wid  = tid >> 5;
    const int wm   = wid >> 2;
    const int wn   = wid & 3;
    const int p0   = blockIdx.x * 128;
    const int jb   = blockIdx.y * 128;

    const __nv_bfloat16* Asrc_h;
    const __nv_bfloat16* Asrc_l;
    int woff;
    if constexpr (MODE == 0) { Asrc_h = xs_h;   Asrc_l = xs_l;   woff = WQ_OFF; }
    else if constexpr (MODE == 1) { Asrc_h = g_aoh;  Asrc_l = g_aol;  woff = WO_OFF; }
    else if constexpr (MODE == 2) { Asrc_h = g_inth; Asrc_l = g_intl; woff = W1_OFF; }
    else { Asrc_h = g_h1h; Asrc_l = g_h1l; woff = W2_OFF; }

    float acc[4][4][4];
    #pragma unroll
    for (int mi = 0; mi < 4; ++mi)
        #pragma unroll
        for (int ni = 0; ni < 4; ++ni)
            #pragma unroll
            for (int q = 0; q < 4; ++q) acc[mi][ni][q] = 0.f;

    auto fill = [&](int c, int st) {
        const int c0 = c * 32;
        __nv_bfloat16* Sg = smb + st * GSTG;
        #pragma unroll
        for (int i = 0; i < 8; ++i) {
            int s = i * 256 + tid;
            int plane = s >> 9;
            int e = s & 511;
            int row = e >> 2, sg = e & 3;
            const __nv_bfloat16* src;
            if (plane == 0) {
                int p = p0 + row; if (p >= PP) p = PP - 1;
                src = &Asrc_h[(size_t)p*256 + c0 + sg*8];
            } else if (plane == 1) {
                int p = p0 + row; if (p >= PP) p = PP - 1;
                src = &Asrc_l[(size_t)p*256 + c0 + sg*8];
            } else if (plane == 2) {
                src = &wsp_h[(size_t)woff + (size_t)(jb + row)*256 + c0 + sg*8];
            } else {
                src = &wsp_l[(size_t)woff + (size_t)(jb + row)*256 + c0 + sg*8];
            }
            cp16(&Sg[plane*5120 + row*40 + sg*8], src);
        }
    };

    // ldmatrix lane geometry
    const int rA = lane & 15;
    const int cA = (lane >> 4) * 8;
    const int rB = (lane & 7) + ((lane >> 4) * 8);
    const int cB = ((lane >> 3) & 1) * 8;

    auto compute = [&](int st) {
        const __nv_bfloat16* base = smb + st * GSTG;
        uint32_t sb = (uint32_t)__cvta_generic_to_shared(base);
        #pragma unroll
        for (int kh = 0; kh < 2; ++kh) {
            const int ko = kh * 16;
            uint32_t bh[4][2], bl[4][2];
            #pragma unroll
            for (int pi = 0; pi < 2; ++pi) {
                uint32_t ab = sb + (uint32_t)(10240 + (wn*32 + pi*16 + rB)*40 + ko + cB)*2;
                LDMX4(bh[2*pi][0], bh[2*pi][1], bh[2*pi+1][0], bh[2*pi+1][1], ab);
                LDMX4(bl[2*pi][0], bl[2*pi][1], bl[2*pi+1][0], bl[2*pi+1][1], ab + 5120*2);
            }
            #pragma unroll
            for (int mi = 0; mi < 4; ++mi) {
                uint32_t aa = sb + (uint32_t)((wm*64 + mi*16 + rA)*40 + ko + cA)*2;
                uint32_t ah0, ah1, ah2, ah3, al0, al1, al2, al3;
                LDMX4(ah0, ah1, ah2, ah3, aa);
                LDMX4(al0, al1, al2, al3, aa + 5120*2);
                #pragma unroll
                for (int ni = 0; ni < 4; ++ni) {
                    MMA_BF16(acc[mi][ni], ah0, ah1, ah2, ah3, bh[ni][0], bh[ni][1]);
                    MMA_BF16(acc[mi][ni], ah0, ah1, ah2, ah3, bl[ni][0], bl[ni][1]);
                    MMA_BF16(acc[mi][ni], al0, al1, al2, al3, bh[ni][0], bh[ni][1]);
                }
            }
        }
    };

    fill(0, 0); CP_COMMIT();
    int st = 0;
    #pragma unroll 1
    for (int c = 0; c < 8; ++c) {
        if (c < 7) { fill(c + 1, st ^ 1); CP_COMMIT(); CP_WAIT1(); }
        else       { CP_WAIT0(); }
        __syncthreads();
        compute(st);
        __syncthreads();
        st ^= 1;
    }

    const int fr = lane >> 2;
    const int fc = (lane & 3) * 2;

    if constexpr (MODE == 0) {
        #pragma unroll
        for (int mi = 0; mi < 4; ++mi) {
            int pr = p0 + wm*64 + mi*16 + fr;
            #pragma unroll
            for (int ni = 0; ni < 4; ++ni) {
                int jc = jb + wn*32 + ni*8 + fc;
                if (pr < PP)
                    store_split2(g_qkvh, g_qkvl, (size_t)pr*768 + jc,
                                 acc[mi][ni][0], acc[mi][ni][1]);
                if (pr + 8 < PP)
                    store_split2(g_qkvh, g_qkvl, (size_t)(pr+8)*768 + jc,
                                 acc[mi][ni][2], acc[mi][ni][3]);
            }
        }
        return;
    }

    float sc[4][2], be[4][2], bo[4][2];
    #pragma unroll
    for (int ni = 0; ni < 4; ++ni)
        #pragma unroll
        for (int q = 0; q < 2; ++q) {
            int j = jb + wn*32 + ni*8 + fc + q;
            float s = rsqrtf(bv[j] + EPSV) * bg[j];
            sc[ni][q] = s;
            be[ni][q] = bb[j] - bm[j] * s;
            bo[ni][q] = (MODE == 1) ? bias[j] : 0.f;
        }

    if constexpr (MODE == 1) {
        #pragma unroll
        for (int mi = 0; mi < 4; ++mi) {
            int pr = p0 + wm*64 + mi*16 + fr;
            #pragma unroll
            for (int ni = 0; ni < 4; ++ni) {
                int jc = jb + wn*32 + ni*8 + fc;
                if (pr < PP) {
                    size_t o = (size_t)pr*256 + jc;
                    float2 xr = load_split2(xs_h, xs_l, o);
                    float v0 = (acc[mi][ni][0] + bo[ni][0] + xr.x)*sc[ni][0] + be[ni][0];
                    float v1 = (acc[mi][ni][1] + bo[ni][1] + xr.y)*sc[ni][1] + be[ni][1];
                    store_split2(g_inth, g_intl, o, v0, v1);
                }
                if (pr + 8 < PP) {
                    size_t o = (size_t)(pr+8)*256 + jc;
                    float2 xr = load_split2(xs_h, xs_l, o);
                    float v2 = (acc[mi][ni][2] + bo[ni][0] + xr.x)*sc[ni][0] + be[ni][0];
                    float v3 = (acc[mi][ni][3] + bo[ni][1] + xr.y)*sc[ni][1] + be[ni][1];
                    store_split2(g_inth, g_intl, o, v2, v3);
                }
            }
        }
        return;
    }

    if constexpr (MODE == 2) {
        #pragma unroll
        for (int mi = 0; mi < 4; ++mi) {
            int pr = p0 + wm*64 + mi*16 + fr;
            #pragma unroll
            for (int ni = 0; ni < 4; ++ni) {
                int jc = jb + wn*32 + ni*8 + fc;
                float v[4];
                #pragma unroll
                for (int q = 0; q < 4; ++q) {
                    float a = acc[mi][ni][q];
                    float sp = (a > 20.f) ? a : log1pf(__expf(a));
                    v[q] = a * tanhf(sp) * sc[ni][q & 1] + be[ni][q & 1];
                }
                if (pr < PP)
                    store_split2(g_h1h, g_h1l, (size_t)pr*256 + jc, v[0], v[1]);
                if (pr + 8 < PP)
                    store_split2(g_h1h, g_h1l, (size_t)(pr+8)*256 + jc, v[2], v[3]);
            }
        }
        return;
    }

    float* stg = (float*)smb;
    #pragma unroll 1
    for (int ph = 0; ph < 2; ++ph) {
        __syncthreads();
        if (wm == ph) {
            #pragma unroll
            for (int mi = 0; mi < 4; ++mi) {
                int lr = mi*16 + fr;
                int pr = p0 + ph*64 + lr;
                int p0c = (pr < PP) ? pr : PP - 1;
                int p1c = (pr + 8 < PP) ? pr + 8 : PP - 1;
                #pragma unroll
                for (int ni = 0; ni < 4; ++ni) {
                    int jl = wn*32 + ni*8 + fc;
                    float2 r0 = load_split2(g_inth, g_intl, (size_t)p0c*256 + jb + jl);
                    float2 r1 = load_split2(g_inth, g_intl, (size_t)p1c*256 + jb + jl);
                    stg[lr*132 + jl]       = (acc[mi][ni][0] + r0.x)*sc[ni][0] + be[ni][0];
                    stg[lr*132 + jl + 1]   = (acc[mi][ni][1] + r0.y)*sc[ni][1] + be[ni][1];
                    stg[(lr+8)*132 + jl]   = (acc[mi][ni][2] + r1.x)*sc[ni][0] + be[ni][0];
                    stg[(lr+8)*132 + jl+1] = (acc[mi][ni][3] + r1.y)*sc[ni][1] + be[ni][1];
                }
            }
        }
        __syncthreads();
        for (int idx = tid; idx < 64 * 128; idx += 256) {
            int pl = idx & 63, j = idx >> 6;
            int p = p0 + ph*64 + pl;
            if (p < PP) {
                int n = p / TV, r = p - n * TV;
                outp[(size_t)(n * CC + jb + j) * TV + r] = stg[pl*132 + j];
            }
        }
    }
}

// ---------------------------------------------------------------------------
// Attention v9 (kept from round 14): offset table + cp.async gathers,
// QK/SV on tensor cores via ldmatrix, exp in registers, shfl row sums.
// smem layout (bf16 elements):
//   QK planes: Qh@0 Ql@5120 Kh@10240 Kl@15360 (stride 40; phases 1-2)
//   P planes:  Ph@0 [128][136], Pl@17408 (overlay QK; phases 3-4)
//   V planes:  Vh@34816 [128][40], Vl@39936
//   T (float idx) @22528: [128][36]; s2d @27136 [4][128]; sums @27648 [128]
//   offs (int idx) @27776: [128]
// Total 27904 floats = 111616 B -> 2 CTAs/SM.
// ---------------------------------------------------------------------------
#define AT_PL   17408
#define AT_VH   34816
#define AT_VL   39936
#define AT_T    22528
#define AT_S2D  27136
#define AT_SUM  27648
#define AT_OFF  27776
#define ATTN_SMEM_FLOATS 27904

__global__ __launch_bounds__(256, 2)
void attn_kernel()
{
    extern __shared__ float smA[];
    __nv_bfloat16* bb_ = (__nv_bfloat16*)smA;
    __nv_bfloat16* Qh = bb_;                 // stride 40
    __nv_bfloat16* Ql = bb_ + 5120;
    __nv_bfloat16* Kh = bb_ + 10240;
    __nv_bfloat16* Kl = bb_ + 15360;
    __nv_bfloat16* Ph = bb_;                 // stride 136 (overlays QK planes)
    __nv_bfloat16* Pl = bb_ + AT_PL;
    __nv_bfloat16* Vh = bb_ + AT_VH;         // [m][40] row-major
    __nv_bfloat16* Vl = bb_ + AT_VL;
    float* T    = smA + AT_T;                // [128][36]
    float* s2d  = smA + AT_S2D;              // [4][128]
    float* sums = smA + AT_SUM;
    int*   offs = (int*)(smA + AT_OFF);      // [128]

    const int tid  = threadIdx.x;
    const int lane = tid & 31;
    const int wid  = tid >> 5;
    const int wm   = wid >> 2;
    const int wn   = wid & 3;
    const int bx = blockIdx.x, h = blockIdx.y;
    const int n = bx / TT, t = bx - n * TT;
    const int fr = lane >> 2;
    const int fc = (lane & 3) * 2;
    // ldmatrix lane geometry
    const int rA = lane & 15;
    const int cA = (lane >> 4) * 8;
    const int rB = (lane & 7) + ((lane >> 4) * 8);
    const int cB = ((lane >> 3) & 1) * 8;
    // trans (V) lane geometry
    const int rT = (lane & 7) + ((lane & 8) ? 8 : 0);
    const int cT = (lane >> 4) * 8;

    // ---- phase 0: per-m source offset table ----
    if (tid < 128) {
        int m = tid;
        int w = m / VVC, vv = m - w * VVC;
        int ti = t + w - 2;
        bool val = (m < LLN) && (ti >= 0) && (ti < TT);
        offs[m] = val ? (((n*TT + ti)*VVC + vv)*768 + h*96) : -1;
    }
    __syncthreads();

    // ---- phase 1: cp.async gathers (table lookup; zfill invalid rows) ----
    for (int lin = tid; lin < 2048; lin += 256) {
        int m = lin >> 4, c = lin & 15;      // c 0-7: q, 8-15: k
        int ofs = offs[m];
        bool val = ofs >= 0;
        int isq   = (c < 8);
        int plane = (c >> 2) & 1;            // 0: hi, 1: lo
        int chunk = c & 3;
        const __nv_bfloat16* srcb = plane ? g_qkvl : g_qkvh;
        __nv_bfloat16* dst = isq ? (plane ? Ql : Qh) : (plane ? Kl : Kh);
        cp16z(&dst[m*40 + chunk*8],
              &srcb[(size_t)(val ? ofs : 0) + (isq ? 0 : 32) + chunk*8], val);
    }
    for (int lin = tid; lin < 1024; lin += 256) {
        int m = lin >> 3, c = lin & 7;
        int ofs = offs[m];
        bool val = ofs >= 0;
        int plane = c >> 2, chunk = c & 3;
        const __nv_bfloat16* srcb = plane ? g_qkvl : g_qkvh;
        __nv_bfloat16* dst = plane ? Vl : Vh;
        cp16z(&dst[m*40 + chunk*8],
              &srcb[(size_t)(val ? ofs : 0) + 64 + chunk*8], val);
    }
    CP_COMMIT();
    CP_WAIT0();
    __syncthreads();

    // ---- phase 2: S = Q K^T (tensor cores, 3-MMA split, ldmatrix) ----
    float acc[4][4][4];
    #pragma unroll
    for (int mi = 0; mi < 4; ++mi)
        #pragma unroll
        for (int ni = 0; ni < 4; ++ni)
            #pragma unroll
            for (int q = 0; q < 4; ++q) acc[mi][ni][q] = 0.f;

    {
        uint32_t sq = (uint32_t)__cvta_generic_to_shared(Qh);
        #pragma unroll
        for (int kh = 0; kh < 2; ++kh) {
            const int ko = kh * 16;
            uint32_t bh[4][2], bl[4][2];
            #pragma unroll
            for (int pi = 0; pi < 2; ++pi) {
                uint32_t ab = sq + (uint32_t)(10240 + (wn*32 + pi*16 + rB)*40 + ko + cB)*2;
                LDMX4(bh[2*pi][0], bh[2*pi][1], bh[2*pi+1][0], bh[2*pi+1][1], ab);
                LDMX4(bl[2*pi][0], bl[2*pi][1], bl[2*pi+1][0], bl[2*pi+1][1], ab + 5120*2);
            }
            #pragma unroll
            for (int mi = 0; mi < 4; ++mi) {
                uint32_t aa = sq + (uint32_t)((wm*64 + mi*16 + rA)*40 + ko + cA)*2;
                uint32_t ah0, ah1, ah2, ah3, al0, al1, al2, al3;
                LDMX4(ah0, ah1, ah2, ah3, aa);
                LDMX4(al0, al1, al2, al3, aa + 5120*2);
                #pragma unroll
                for (int ni = 0; ni < 4; ++ni) {
                    MMA_BF16(acc[mi][ni], ah0, ah1, ah2, ah3, bh[ni][0], bh[ni][1]);
                    MMA_BF16(acc[mi][ni], ah0, ah1, ah2, ah3, bl[ni][0], bl[ni][1]);
                    MMA_BF16(acc[mi][ni], al0, al1, al2, al3, bh[ni][0], bh[ni][1]);
                }
            }
        }
    }
    __syncthreads();   // QK planes dead; safe to overlay P

    // ---- phase 3: exp in registers -> P planes + row-sum partials ----
    #pragma unroll
    for (int mi = 0; mi < 4; ++mi) {
        int r0 = wm*64 + mi*16 + fr;
        int r1 = r0 + 8;
        float s0 = 0.f, s1 = 0.f;
        #pragma unroll
        for (int ni = 0; ni < 4; ++ni) {
            int jc = wn*32 + ni*8 + fc;
            float p0 = (jc     >= LLN) ? 0.f : __expf(acc[mi][ni][0] * 0.0625f);
            float p1 = (jc + 1 >= LLN) ? 0.f : __expf(acc[mi][ni][1] * 0.0625f);
            float p2 = (jc     >= LLN) ? 0.f : __expf(acc[mi][ni][2] * 0.0625f);
            float p3 = (jc + 1 >= LLN) ? 0.f : __expf(acc[mi][ni][3] * 0.0625f);
            store_split2(Ph, Pl, (size_t)r0*136 + jc, p0, p1);
            store_split2(Ph, Pl, (size_t)r1*136 + jc, p2, p3);
            s0 += p0 + p1;
            s1 += p2 + p3;
        }
        s0 += __shfl_xor_sync(0xffffffffu, s0, 1);
        s0 += __shfl_xor_sync(0xffffffffu, s0, 2);
        s1 += __shfl_xor_sync(0xffffffffu, s1, 1);
        s1 += __shfl_xor_sync(0xffffffffu, s1, 2);
        if ((lane & 3) == 0) {
            s2d[wn*128 + r0] = s0;
            s2d[wn*128 + r1] = s1;
        }
    }
    __syncthreads();

    // ---- phase 4: combine row sums, then SV MMA: T = P.V ----
    if (tid < LLN)
        sums[tid] = 0.2f / (s2d[tid] + s2d[128 + tid] + s2d[256 + tid] + s2d[384 + tid]);

    float accS[4][4];
    #pragma unroll
    for (int ni = 0; ni < 4; ++ni)
        #pragma unroll
        for (int q = 0; q < 4; ++q) accS[ni][q] = 0.f;

    {
        uint32_t sp_ = (uint32_t)__cvta_generic_to_shared(Ph);
        uint32_t sv_ = (uint32_t)__cvta_generic_to_shared(Vh);
        #pragma unroll
        for (int kh = 0; kh < 8; ++kh) {
            const int ko = kh * 16;
            uint32_t bh[4][2], bl[4][2];
            #pragma unroll
            for (int pi = 0; pi < 2; ++pi) {
                uint32_t ab = sv_ + (uint32_t)((ko + rT)*40 + pi*16 + cT)*2;
                LDMX4T(bh[2*pi][0], bh[2*pi][1], bh[2*pi+1][0], bh[2*pi+1][1], ab);
                LDMX4T(bl[2*pi][0], bl[2*pi][1], bl[2*pi+1][0], bl[2*pi+1][1],
                       ab + (AT_VL - AT_VH)*2);
            }
            uint32_t aa = sp_ + (uint32_t)((wid*16 + rA)*136 + ko + cA)*2;
            uint32_t ah0, ah1, ah2, ah3, al0, al1, al2, al3;
            LDMX4(ah0, ah1, ah2, ah3, aa);
            LDMX4(al0, al1, al2, al3, aa + AT_PL*2);
            #pragma unroll
            for (int ni = 0; ni < 4; ++ni) {
                MMA_BF16(accS[ni], ah0, ah1, ah2, ah3, bh[ni][0], bh[ni][1]);
                MMA_BF16(accS[ni], ah0, ah1, ah2, ah3, bl[ni][0], bl[ni][1]);
                MMA_BF16(accS[ni], al0, al1, al2, al3, bh[ni][0], bh[ni][1]);
            }
        }
    }
    // write T
    #pragma unroll
    for (int ni = 0; ni < 4; ++ni) {
        int col = ni*8 + fc;
        int row = wid*16 + fr;
        *(float2*)&T[row*36 + col]     = make_float2(accS[ni][0], accS[ni][1]);
        *(float2*)&T[(row+8)*36 + col] = make_float2(accS[ni][2], accS[ni][3]);
    }
    __syncthreads();

    // ---- phase 5: O[v,d] = sum_w T[w*25+v,d] * (0.2/sum) -> g_ao planes ----
    if (tid < 200) {
        const int v = tid >> 3, g = tid & 7;
        float4 a4 = make_float4(0.f, 0.f, 0.f, 0.f);
        #pragma unroll
        for (int w = 0; w < 5; ++w) {
            int l = w*VVC + v;
            float rs = sums[l];
            float4 tv = *(const float4*)&T[l*36 + g*4];
            a4.x = fmaf(tv.x, rs, a4.x); a4.y = fmaf(tv.y, rs, a4.y);
            a4.z = fmaf(tv.z, rs, a4.z); a4.w = fmaf(tv.w, rs, a4.w);
        }
        size_t base = ((size_t)((n*TT + t)*VVC + v))*256 + h*HD + g*4;
        store_split2(g_aoh, g_aol, base,     a4.x, a4.y);
        store_split2(g_aoh, g_aol, base + 2, a4.z, a4.w);
    }
}

// ---------------------------------------------------------------------------
extern "C" void kernel_launch(void* const* d_in, const int* in_sizes, int n_in,
                              void* d_out, int out_size)
{
    const float* x      = (const float*)d_in[0];
    const float* w_qkv  = (const float*)d_in[1];
    const float* w_out  = (const float*)d_in[2];
    const float* b_out  = (const float*)d_in[3];
    const float* bn1_g  = (const float*)d_in[4];
    const float* bn1_b  = (const float*)d_in[5];
    const float* ffn_w1 = (const float*)d_in[6];
    const float* ffn_w2 = (const float*)d_in[7];
    const float* ffn_g  = (const float*)d_in[8];
    const float* ffn_b  = (const float*)d_in[9];
    const float* bn2_g  = (const float*)d_in[10];
    const float* bn2_b  = (const float*)d_in[11];
    const float* bn1_m  = (const float*)d_in[12];
    const float* bn1_v  = (const float*)d_in[13];
    const float* ffn_m  = (const float*)d_in[14];
    const float* ffn_v  = (const float*)d_in[15];
    const float* bn2_m  = (const float*)d_in[16];
    const float* bn2_v  = (const float*)d_in[17];
    float* out = (float*)d_out;

    static int attr_done = 0;
    if (!attr_done) {
        cudaFuncSetAttribute(attn_kernel,
            cudaFuncAttributeMaxDynamicSharedMemorySize, ATTN_SMEM_FLOATS * 4);
        cudaFuncSetAttribute(prep_x,
            cudaFuncAttributeMaxDynamicSharedMemorySize, PXSMEM);
        cudaFuncSetAttribute(mma_gemm<0>,
            cudaFuncAttributeMaxDynamicSharedMemorySize, GSMEM);
        cudaFuncSetAttribute(mma_gemm<1>,
            cudaFuncAttributeMaxDynamicSharedMemorySize, GSMEM);
        cudaFuncSetAttribute(mma_gemm<2>,
            cudaFuncAttributeMaxDynamicSharedMemorySize, GSMEM);
        cudaFuncSetAttribute(mma_gemm<3>,
            cudaFuncAttributeMaxDynamicSharedMemorySize, GSMEM);
        attr_done = 1;
    }

    const int MT = (PP + 127) / 128;   // 188 M-tiles

    prep_w<<<(WTOT + 255)/256, 256>>>(w_qkv, w_out, ffn_w1, ffn_w2);
    prep_x<<<PP/64, 256, PXSMEM>>>(x);

    mma_gemm<0><<<dim3(MT, 6), 256, GSMEM>>>(
        nullptr, nullptr, nullptr, nullptr, nullptr, nullptr);

    attn_kernel<<<dim3(NB*TT, HH), 256, ATTN_SMEM_FLOATS * 4>>>();

    mma_gemm<1><<<dim3(MT, 2), 256, GSMEM>>>(
        b_out, bn1_g, bn1_b, bn1_m, bn1_v, nullptr);

    mma_gemm<2><<<dim3(MT, 2), 256, GSMEM>>>(
        nullptr, ffn_g, ffn_b, ffn_m, ffn_v, nullptr);

    mma_gemm<3><<<dim3(MT, 2), 256, GSMEM>>>(
        nullptr, bn2_g, bn2_b, bn2_m, bn2_v, out);
}